// round 16
// baseline (speedup 1.0000x reference)
#include <cuda_runtime.h>
#include <cuda_fp16.h>
#include <cstdint>
#include <cstddef>

#define HW    10000
#define WID   100
#define NPAD  10240
#define KTOT  2304
#define WROWS 3584
#define CSTR  ((size_t)NPAD * KTOT)
#define CH112 11312
#define NPIX  11200
#define FC4   ((size_t)4 * 256 * CH112)
#define FGUARD 128

__device__ __half g_wfh[WROWS * KTOT];
__device__ __half g_wfl[WROWS * KTOT];
__device__ __half g_catc[2 * CSTR];
__device__ __half g_catr[2 * CSTR];
__device__ __half g_fA[FGUARD + 3 * FC4 + 256];
__device__ __half g_fB[FGUARD + 3 * FC4 + 256];
__device__ float g_f32[(size_t)4 * 256 * CH112];
__device__ float g_boxreg[2 * 36 * HW];
__device__ float g_refine[2 * 36 * HW];

__constant__ float c_AW[9] = {
    2.8284271247461903f, 2.0f, 1.4142135623730951f,
    3.5635948725613580f, 2.5198420997897464f, 1.7817974362806790f,
    4.4898481932374910f, 3.1748021039363988f, 2.2449240966187455f};
__constant__ float c_AH[9] = {
    1.4142135623730951f, 2.0f, 2.8284271247461903f,
    1.7817974362806790f, 2.5198420997897464f, 3.5635948725613580f,
    2.2449240966187455f, 3.1748021039363988f, 4.4898481932374910f};
__constant__ int c_dy9[9]   = {-1,-1,-1, 0,0,0, 1,1,1};
__constant__ int c_dxsel[9] = { 0, 1, 2, 0,1,2, 0,1,2};

__device__ __forceinline__ uint32_t smem_u32(const void* p) {
    uint32_t a;
    asm("{ .reg .u64 t; cvta.to.shared.u64 t, %1; cvt.u32.u64 %0, t; }" : "=r"(a) : "l"(p));
    return a;
}
__device__ __forceinline__ void cp16(uint32_t dst, const void* src) {
    asm volatile("cp.async.cg.shared.global [%0], [%1], 16;" :: "r"(dst), "l"(src));
}
__device__ __forceinline__ void ldmx4(uint32_t* r, uint32_t addr) {
    asm volatile("ldmatrix.sync.aligned.m8n8.x4.shared.b16 {%0,%1,%2,%3}, [%4];"
                 : "=r"(r[0]), "=r"(r[1]), "=r"(r[2]), "=r"(r[3]) : "r"(addr));
}
__device__ __forceinline__ void ldmx4t(uint32_t* r, uint32_t addr) {
    asm volatile("ldmatrix.sync.aligned.m8n8.x4.trans.shared.b16 {%0,%1,%2,%3}, [%4];"
                 : "=r"(r[0]), "=r"(r[1]), "=r"(r[2]), "=r"(r[3]) : "r"(addr));
}
__device__ __forceinline__ void mma_hf(float* c, const uint32_t* a, uint32_t b0, uint32_t b1) {
    asm volatile("mma.sync.aligned.m16n8k16.row.col.f32.f16.f16.f32 "
                 "{%0,%1,%2,%3}, {%4,%5,%6,%7}, {%8,%9}, {%0,%1,%2,%3};"
                 : "+f"(c[0]), "+f"(c[1]), "+f"(c[2]), "+f"(c[3])
                 : "r"(a[0]), "r"(a[1]), "r"(a[2]), "r"(a[3]), "r"(b0), "r"(b1));
}
__device__ __forceinline__ uint32_t hpack(__half a, __half b) {
    return (uint32_t)__half_as_ushort(a) | ((uint32_t)__half_as_ushort(b) << 16);
}
__device__ __forceinline__ uint32_t sw_off(int r, int c) {
    return (uint32_t)((r * 4 + (c ^ (r & 3))) << 4);
}
__device__ __forceinline__ uint32_t swb_off(int r, int c) {
    return (uint32_t)((r * 16 + (c ^ (r & 7))) << 4);
}

#define TILE_B 8192
#define NSTG 3
#define NK   72
#define STAGE_F (3 * TILE_B)
#define SMEM_F (NSTG * STAGE_F)        // 72 KB (conv_f16 / gemm_f16)

// fused deform smem: A stages 3x16K=48K | B dbl buf 2x8K=16K | table 27.65K
#define D_AOFF 0
#define D_ASTG (2 * TILE_B)
#define D_BOFF (NSTG * D_ASTG)          // 49152
#define D_TOFF (D_BOFF + 2 * TILE_B)    // 65536
#define SMEM_D (D_TOFF + 6 * 1152 * 4)  // 93184 -> 2 CTAs/SM

// ============ fp16 2-term GEMM, explicit B [rows,K] (heads) ============
__global__ __launch_bounds__(256, 2) void gemm_f16(
    const __half* __restrict__ Wh, const __half* __restrict__ Wl, int arow,
    const __half* __restrict__ Bbase,
    const float* __restrict__ bias,
    float* __restrict__ outF, size_t outStride, int M)
{
    extern __shared__ char smem[];
    const uint32_t sb = smem_u32(smem);
    const int tid = threadIdx.x, lane = tid & 31, w = tid >> 5;
    const int wm = w >> 2, wn = w & 3;
    const int m0 = blockIdx.y * 128, n0 = blockIdx.x * 128;
    const int z = blockIdx.z;

    const __half* srcA[2] = {Wh + ((size_t)arow + m0) * KTOT, Wl + ((size_t)arow + m0) * KTOT};
    const __half* srcB = Bbase + (size_t)z * CSTR + (size_t)n0 * KTOT;

    float acc[4][4][4];
#pragma unroll
    for (int i = 0; i < 4; i++)
#pragma unroll
        for (int j = 0; j < 4; j++)
#pragma unroll
            for (int q = 0; q < 4; q++) acc[i][j][q] = 0.f;

    const int ra = (lane & 15), ca = lane >> 4;
    const int rb = (lane & 7) + ((lane >> 4) << 3), cb = (lane >> 3) & 1;

#define LOAD_STAGE(s, k0) do { \
    _Pragma("unroll") \
    for (int tt = 0; tt < 2; tt++) { \
        const uint32_t base = sb + (uint32_t)((s) * STAGE_F + tt * TILE_B); \
        _Pragma("unroll") \
        for (int h = 0; h < 2; h++) { \
            const int q = tid + h * 256; \
            const int r = q >> 2, c = q & 3; \
            cp16(base + sw_off(r, c), srcA[tt] + (size_t)r * KTOT + (k0) + c * 8); \
        } \
    } \
    { \
        const uint32_t base = sb + (uint32_t)((s) * STAGE_F + 2 * TILE_B); \
        _Pragma("unroll") \
        for (int h = 0; h < 2; h++) { \
            const int q = tid + h * 256; \
            const int r = q >> 2, c = q & 3; \
            cp16(base + sw_off(r, c), srcB + (size_t)r * KTOT + (k0) + c * 8); \
        } \
    } \
} while (0)

    LOAD_STAGE(0, 0);
    asm volatile("cp.async.commit_group;" ::: "memory");
    LOAD_STAGE(1, 32);
    asm volatile("cp.async.commit_group;" ::: "memory");

    for (int kc = 0; kc < NK; kc++) {
        asm volatile("cp.async.wait_group 1;" ::: "memory");
        __syncthreads();
        const uint32_t bA  = sb + (uint32_t)((kc % NSTG) * STAGE_F);
        const uint32_t bAl = bA + TILE_B;
        const uint32_t bB  = bA + 2 * TILE_B;
#pragma unroll
        for (int kh = 0; kh < 2; kh++) {
            uint32_t fb[2][4];
#pragma unroll
            for (int nt2 = 0; nt2 < 2; nt2++) {
                const int rr = wn * 32 + nt2 * 16 + rb;
                ldmx4(fb[nt2], bB + sw_off(rr, kh * 2 + cb));
            }
#pragma unroll
            for (int mt = 0; mt < 4; mt++) {
                uint32_t fah[4], fal[4];
                const int rr = wm * 64 + mt * 16 + ra;
                ldmx4(fah, bA  + sw_off(rr, kh * 2 + ca));
                ldmx4(fal, bAl + sw_off(rr, kh * 2 + ca));
#pragma unroll
                for (int nt = 0; nt < 4; nt++) {
                    const uint32_t b0 = fb[nt >> 1][(nt & 1) * 2];
                    const uint32_t b1 = fb[nt >> 1][(nt & 1) * 2 + 1];
                    mma_hf(acc[mt][nt], fah, b0, b1);
                    mma_hf(acc[mt][nt], fal, b0, b1);
                }
            }
        }
        if (kc + 2 < NK) LOAD_STAGE((kc + 2) % NSTG, (kc + 2) * 32);
        asm volatile("cp.async.commit_group;" ::: "memory");
    }
    __syncthreads();
#undef LOAD_STAGE

    const int group = lane >> 2, tid4 = lane & 3;
    float* oF = outF + (size_t)z * outStride;
#pragma unroll
    for (int mt = 0; mt < 4; mt++) {
        const int mA = m0 + wm * 64 + mt * 16 + group;
        const int mB = mA + 8;
        const float bvA = (mA < M) ? bias[mA] : 0.f;
        const float bvB = (mB < M) ? bias[mB] : 0.f;
#pragma unroll
        for (int nt = 0; nt < 4; nt++) {
            const int n = n0 + wn * 32 + nt * 8 + tid4 * 2;
#pragma unroll
            for (int e = 0; e < 2; e++) {
                if (n + e < HW) {
                    if (mA < M) oF[(size_t)mA * HW + n + e] = acc[mt][nt][e] + bvA;
                    if (mB < M) oF[(size_t)mB * HW + n + e] = acc[mt][nt][2 + e] + bvB;
                }
            }
        }
    }
}

// ============ FUSED deform conv GEMM ============
// z = dIdx*2 + t ; B gathered in-kernel from fp32 features; cat fp16 out.
__global__ __launch_bounds__(256, 2) void deform_conv_f16(
    const __half* __restrict__ Wh, const __half* __restrict__ Wl, int arowC, int arowR,
    const float* __restrict__ f32, const float* __restrict__ boxreg,
    __half* __restrict__ catc, __half* __restrict__ catr)
{
    extern __shared__ char smem[];
    const uint32_t sb = smem_u32(smem);
    const int tid = threadIdx.x, lane = tid & 31, w = tid >> 5;
    const int wm = w >> 2, wn = w & 3;
    const int m0 = blockIdx.y * 128, n0 = blockIdx.x * 128;
    const int z = blockIdx.z;
    const int t = z & 1, dIdx = z >> 1;
    const int bpp = dIdx / 9, ap = dIdx % 9;
    const int nn = ap * 2 + bpp, bb = nn / 9, aa = nn % 9;
    const int arow = t ? arowR : arowC;

    const __half* srcA[2] = {Wh + ((size_t)arow + m0) * KTOT, Wl + ((size_t)arow + m0) * KTOT};
    const float* fsrc = f32 + (size_t)((bpp * 2 + t) * 256) * CH112;

    float* tw00 = (float*)(smem + D_TOFF);
    float* tw01 = tw00 + 1152;
    float* tw10 = tw01 + 1152;
    float* tw11 = tw10 + 1152;
    int*   to00 = (int*)(tw11 + 1152);
    int*   tdxy = to00 + 1152;
    float* pxt  = (float*)(smem + D_BOFF);   // temp, overwritten by B later

    // A prefetch stages 0,1
#define LOAD_A(s, kc) do { \
    _Pragma("unroll") \
    for (int tt = 0; tt < 2; tt++) { \
        const uint32_t base = sb + (uint32_t)(D_AOFF + (s) * D_ASTG + tt * TILE_B); \
        _Pragma("unroll") \
        for (int h = 0; h < 2; h++) { \
            const int q = tid + h * 256; \
            const int r = q >> 2, c = q & 3; \
            cp16(base + sw_off(r, c), srcA[tt] + (size_t)r * KTOT + (kc) * 32 + c * 8); \
        } \
    } \
} while (0)
    LOAD_A(0, 0);
    asm volatile("cp.async.commit_group;" ::: "memory");
    LOAD_A(1, 1);
    asm volatile("cp.async.commit_group;" ::: "memory");

    // step1: per-px grid coords
    if (tid < 128) {
        const int p = n0 + tid;
        float g[6] = {0, 0, 0, 0, 0, 0};
        if (p < HW) {
            const float aw = c_AW[aa], ah_ = c_AH[aa];
            const float* br = boxreg + (size_t)bb * 36 * HW + (size_t)aa * 4 * HW + p;
            const float r0 = br[0], r1 = br[HW], r2 = br[2 * HW], r3 = br[3 * HW];
            const float whx = aw * expf(r2), why = ah_ * expf(r3);
            const float tlx = aw * r0 - 0.5f * whx, tly = ah_ * r1 - 0.5f * why;
            g[0] = tlx; g[1] = tlx + 0.5f * whx; g[2] = tlx + whx;        // gxv
            g[3] = tly; g[4] = tly + 0.5f * why; g[5] = tly + why;        // gyv
        }
#pragma unroll
        for (int q = 0; q < 6; q++) pxt[tid * 8 + q] = g[q];
    }
    __syncthreads();

    // step2: per (tap, px) bilinear table
    for (int e = tid; e < 1152; e += 256) {
        const int tap = e >> 7, px = e & 127;
        const int p = n0 + px;
        float w00 = 0.f, w01 = 0.f, w10 = 0.f, w11 = 0.f;
        int o00 = 0, dxy = 0;
        if (p < HW) {
            const int y = p / WID, x = p % WID;
            const int i = tap / 3, j = tap % 3;
            const float pxf = (float)x + pxt[px * 8 + 3 + i];   // gyv[i]
            const float pyf = (float)y + pxt[px * 8 + j];       // gxv[j]
            const float x0f = floorf(pxf), y0f = floorf(pyf);
            const float lx = pxf - x0f, ly = pyf - y0f;
            const int ix0 = (int)x0f, iy0 = (int)y0f;
            const bool vx0 = (ix0 >= 0) && (ix0 < WID), vx1 = (ix0 >= -1) && (ix0 + 1 < WID);
            const bool vy0 = (iy0 >= 0) && (iy0 < WID), vy1 = (iy0 >= -1) && (iy0 + 1 < WID);
            const int xc0 = min(max(ix0, 0), WID - 1), xc1 = min(max(ix0 + 1, 0), WID - 1);
            const int yc0 = min(max(iy0, 0), WID - 1), yc1 = min(max(iy0 + 1, 0), WID - 1);
            w00 = (vy0 && vx0) ? (1.f - ly) * (1.f - lx) : 0.f;
            w01 = (vy0 && vx1) ? (1.f - ly) * lx : 0.f;
            w10 = (vy1 && vx0) ? ly * (1.f - lx) : 0.f;
            w11 = (vy1 && vx1) ? ly * lx : 0.f;
            o00 = yc0 * 112 + xc0;
            dxy = (xc1 - xc0) | (((yc1 - yc0) * 112) << 16);
        }
        tw00[e] = w00; tw01[e] = w01; tw10[e] = w10; tw11[e] = w11;
        to00[e] = o00; tdxy[e] = dxy;
    }
    __syncthreads();

    float acc[4][4][4];
#pragma unroll
    for (int i = 0; i < 4; i++)
#pragma unroll
        for (int j = 0; j < 4; j++)
#pragma unroll
            for (int q = 0; q < 4; q++) acc[i][j][q] = 0.f;

    const int ra = (lane & 15), ca = lane >> 4;
    const int rbb = (lane & 7) + ((lane >> 4) << 3), cbb = (lane >> 3) & 1;

    for (int kc = 0; kc < NK; kc++) {
        // produce B[kc&1]: tap = kc/8, channels c0..c0+31
        {
            const int tap = kc >> 3, c0 = (kc & 7) << 5;
            char* bBp = smem + D_BOFF + (kc & 1) * TILE_B;
#pragma unroll
            for (int v = 0; v < 2; v++) {
                const int sidx = tid + v * 256;
                const int px = sidx >> 2, c4 = sidx & 3;
                const int e = tap * 128 + px;
                const float w00 = tw00[e], w01 = tw01[e], w10 = tw10[e], w11 = tw11[e];
                const int o00 = to00[e], dxy = tdxy[e];
                const int dx = dxy & 0xffff, dyy = dxy >> 16;
                const float* f = fsrc + (size_t)(c0 + c4 * 8) * CH112;
                __half hs[8];
#pragma unroll
                for (int j = 0; j < 8; j++) {
                    const float val = w00 * f[o00] + w01 * f[o00 + dx]
                                    + w10 * f[o00 + dyy] + w11 * f[o00 + dx + dyy];
                    hs[j] = __float2half_rn(val);
                    f += CH112;
                }
                *(uint4*)(bBp + sw_off(px, c4)) =
                    make_uint4(hpack(hs[0], hs[1]), hpack(hs[2], hs[3]),
                               hpack(hs[4], hs[5]), hpack(hs[6], hs[7]));
            }
        }
        asm volatile("cp.async.wait_group 1;" ::: "memory");
        __syncthreads();

        const uint32_t bA  = sb + (uint32_t)(D_AOFF + (kc % NSTG) * D_ASTG);
        const uint32_t bAl = bA + TILE_B;
        const uint32_t bB  = sb + (uint32_t)(D_BOFF + (kc & 1) * TILE_B);
#pragma unroll
        for (int kh = 0; kh < 2; kh++) {
            uint32_t fb[2][4];
#pragma unroll
            for (int nt2 = 0; nt2 < 2; nt2++) {
                const int rr = wn * 32 + nt2 * 16 + rbb;
                ldmx4(fb[nt2], bB + sw_off(rr, kh * 2 + cbb));
            }
#pragma unroll
            for (int mt = 0; mt < 4; mt++) {
                uint32_t fah[4], fal[4];
                const int rr = wm * 64 + mt * 16 + ra;
                ldmx4(fah, bA  + sw_off(rr, kh * 2 + ca));
                ldmx4(fal, bAl + sw_off(rr, kh * 2 + ca));
#pragma unroll
                for (int nt = 0; nt < 4; nt++) {
                    const uint32_t b0 = fb[nt >> 1][(nt & 1) * 2];
                    const uint32_t b1 = fb[nt >> 1][(nt & 1) * 2 + 1];
                    mma_hf(acc[mt][nt], fah, b0, b1);
                    mma_hf(acc[mt][nt], fal, b0, b1);
                }
            }
        }
        if (kc + 2 < NK) LOAD_A((kc + 2) % NSTG, kc + 2);
        asm volatile("cp.async.commit_group;" ::: "memory");
        __syncthreads();   // B[kc&1] fully consumed before iter kc+2 overwrites it
    }
#undef LOAD_A

    // cat epilogue (transpose through smem, fp16 + relu)
    const int group = lane >> 2, tid4 = lane & 3;
    __half* outT = t ? catr : catc;
    float* smf = (float*)smem;
#pragma unroll
    for (int mt = 0; mt < 4; mt++)
#pragma unroll
        for (int nt = 0; nt < 4; nt++) {
            const int ml = wm * 64 + mt * 16 + group;
            const int nl = wn * 32 + nt * 8 + tid4 * 2;
            smf[nl * 128 + ml]           = acc[mt][nt][0];
            smf[(nl + 1) * 128 + ml]     = acc[mt][nt][1];
            smf[nl * 128 + ml + 8]       = acc[mt][nt][2];
            smf[(nl + 1) * 128 + ml + 8] = acc[mt][nt][3];
        }
    __syncthreads();
    const int nl = tid >> 1, half = tid & 1;
    const float* row = smf + nl * 128 + half * 64;
    __half* oh = outT + (size_t)(bpp * NPAD + n0 + nl) * KTOT + ap * 256 + m0 + half * 64;
#pragma unroll
    for (int g = 0; g < 8; g++) {
        __half hs[8];
#pragma unroll
        for (int j = 0; j < 8; j++)
            hs[j] = __float2half_rn(fmaxf(row[g * 8 + j], 0.f));
        *(uint4*)(oh + g * 8) = make_uint4(hpack(hs[0], hs[1]), hpack(hs[2], hs[3]),
                                           hpack(hs[4], hs[5]), hpack(hs[6], hs[7]));
    }
}

// ============ fp16 2-term implicit conv GEMM (towers + pred), unchanged R15 ============
// flags: 1=bias 2=relu 8=z-parity 16=feat-out 32=fp32-p-out 64=also f32 copy
__global__ __launch_bounds__(256, 2) void conv_f16(
    const __half* __restrict__ Wh, const __half* __restrict__ Wl, int arowE, int arowO,
    const __half* __restrict__ fIn, int cmul, int cadd, int cshift,
    const float* __restrict__ biasE, const float* __restrict__ biasO,
    float* __restrict__ outF, size_t outStride,
    __half* __restrict__ oFeat, float* __restrict__ oF32,
    int M, int flags)
{
    extern __shared__ char smem[];
    const uint32_t sb = smem_u32(smem);
    const int tid = threadIdx.x, lane = tid & 31, w = tid >> 5;
    const int wm = w >> 2, wn = w & 3;
    const int m0 = blockIdx.y * 128, n0 = blockIdx.x * 128;
    const int z = blockIdx.z;
    const int inChain = ((z * cmul) + cadd) >> cshift;

    const bool odd = (flags & 8) && (z & 1);
    const int arow = odd ? arowO : arowE;
    const float* bias = odd ? biasO : biasE;

    const __half* srcA[2] = {Wh + ((size_t)arow + m0) * KTOT, Wl + ((size_t)arow + m0) * KTOT};
    const __half* fbase = fIn + (size_t)inChain * 256 * CH112 + n0;

    float acc[4][4][4];
#pragma unroll
    for (int i = 0; i < 4; i++)
#pragma unroll
        for (int j = 0; j < 4; j++)
#pragma unroll
            for (int q = 0; q < 4; q++) acc[i][j][q] = 0.f;

    const int ra = (lane & 15), ca = lane >> 4;

#define LOAD_CSTAGE(s, kc) do { \
    const int _t = (kc) >> 3, _c0 = ((kc) & 7) << 5; \
    const long _toff = (long)c_dxsel[_t] * (long)FC4 + (long)c_dy9[_t] * 112; \
    _Pragma("unroll") \
    for (int t2 = 0; t2 < 2; t2++) { \
        const uint32_t baseA = sb + (uint32_t)((s) * STAGE_F + t2 * TILE_B); \
        _Pragma("unroll") \
        for (int h = 0; h < 2; h++) { \
            const int q = tid + h * 256; \
            const int r = q >> 2, c = q & 3; \
            cp16(baseA + sw_off(r, c), srcA[t2] + (size_t)r * KTOT + (kc) * 32 + c * 8); \
        } \
    } \
    { \
        const uint32_t baseB = sb + (uint32_t)((s) * STAGE_F + 2 * TILE_B); \
        _Pragma("unroll") \
        for (int h = 0; h < 2; h++) { \
            const int q = tid + h * 256; \
            const int r = q >> 4, c = q & 15; \
            cp16(baseB + swb_off(r, c), fbase + _toff + (size_t)(_c0 + r) * CH112 + c * 8); \
        } \
    } \
} while (0)

    LOAD_CSTAGE(0, 0);
    asm volatile("cp.async.commit_group;" ::: "memory");
    LOAD_CSTAGE(1, 1);
    asm volatile("cp.async.commit_group;" ::: "memory");

    for (int kc = 0; kc < NK; kc++) {
        asm volatile("cp.async.wait_group 1;" ::: "memory");
        __syncthreads();
        const uint32_t bA  = sb + (uint32_t)((kc % NSTG) * STAGE_F);
        const uint32_t bAl = bA + TILE_B;
        const uint32_t bB  = bA + 2 * TILE_B;
#pragma unroll
        for (int kh = 0; kh < 2; kh++) {
            const int rowl = kh * 16 + (lane & 15);
            uint32_t fb[2][4];
#pragma unroll
            for (int nt2 = 0; nt2 < 2; nt2++) {
                const int chunk = wn * 4 + nt2 * 2 + (lane >> 4);
                ldmx4t(fb[nt2], bB + swb_off(rowl, chunk));
            }
#pragma unroll
            for (int mt = 0; mt < 4; mt++) {
                uint32_t fah[4], fal[4];
                const int rr = wm * 64 + mt * 16 + ra;
                ldmx4(fah, bA  + sw_off(rr, kh * 2 + ca));
                ldmx4(fal, bAl + sw_off(rr, kh * 2 + ca));
#pragma unroll
                for (int nt = 0; nt < 4; nt++) {
                    const uint32_t b0 = fb[nt >> 1][(nt & 1) * 2];
                    const uint32_t b1 = fb[nt >> 1][(nt & 1) * 2 + 1];
                    mma_hf(acc[mt][nt], fah, b0, b1);
                    mma_hf(acc[mt][nt], fal, b0, b1);
                }
            }
        }
        if (kc + 2 < NK) LOAD_CSTAGE((kc + 2) % NSTG, kc + 2);
        asm volatile("cp.async.commit_group;" ::: "memory");
    }
    __syncthreads();
#undef LOAD_CSTAGE

    const int group = lane >> 2, tid4 = lane & 3;
#pragma unroll
    for (int mt = 0; mt < 4; mt++) {
        const int mA = m0 + wm * 64 + mt * 16 + group;
        const int mB = mA + 8;
        const float bvA = ((flags & 1) && mA < M) ? bias[mA] : 0.f;
        const float bvB = ((flags & 1) && mB < M) ? bias[mB] : 0.f;
#pragma unroll
        for (int nt = 0; nt < 4; nt++) {
            const int n = n0 + wn * 32 + nt * 8 + tid4 * 2;
#pragma unroll
            for (int e = 0; e < 2; e++) {
                const int p2 = n + e;
                if (p2 >= NPIX) continue;
                const int xq = p2 % 112;
                if (xq >= 100) continue;
                if (flags & 16) {
#pragma unroll
                    for (int half = 0; half < 2; half++) {
                        const int m = half ? mB : mA;
                        float v = (half ? acc[mt][nt][2 + e] : acc[mt][nt][e]) + (half ? bvB : bvA);
                        v = fmaxf(v, 0.f);
                        const __half h = __float2half_rn(v);
                        const size_t cb = (size_t)(z * 256 + m) * CH112;
                        if (flags & 64) oF32[cb + p2] = v;
#pragma unroll
                        for (int j = 0; j < 3; j++) {
                            const int q = p2 - (j - 1);
                            if (q >= 0) oFeat[(size_t)j * FC4 + cb + q] = h;
                        }
                    }
                } else {
                    const int p = (p2 / 112) * 100 + xq;
                    float* oF = outF + (size_t)z * outStride;
                    if (mA < M) oF[(size_t)mA * HW + p] = acc[mt][nt][e] + bvA;
                    if (mB < M) oF[(size_t)mB * HW + p] = acc[mt][nt][2 + e] + bvB;
                }
            }
        }
    }
}

// ============ small kernels ============
__global__ void wsplit_f16(const float* __restrict__ src, __half* __restrict__ h,
                           __half* __restrict__ l, int M, int Mp, int tap)
{
    const int idx = blockIdx.x * blockDim.x + threadIdx.x;
    if (idx >= Mp * KTOT) return;
    const int m = idx / KTOT, kk = idx % KTOT;
    float v = 0.f;
    if (m < M) {
        const int ks = tap ? ((kk & 255) * 9 + (kk >> 8)) : kk;
        v = src[(size_t)m * KTOT + ks];
    }
    const __half hh = __float2half_rn(v);
    h[idx] = hh;
    l[idx] = __float2half_rn(v - __half2float(hh));
}

__global__ void xsplit3_f16(const float* __restrict__ x, __half* __restrict__ o)
{
    const int idx = blockIdx.x * blockDim.x + threadIdx.x;
    if (idx >= 2 * 256 * NPIX) return;
    const int p2 = idx % NPIX;
    const int ch = idx / NPIX;
    const int xq = p2 % 112;
    if (xq >= 100) return;
    const float v = x[(size_t)ch * HW + (p2 / 112) * 100 + xq];
    const __half h = __float2half_rn(v);
    const size_t cb = (size_t)ch * CH112;
#pragma unroll
    for (int j = 0; j < 3; j++) {
        const int q = p2 - (j - 1);
        if (q >= 0) o[(size_t)j * FC4 + cb + q] = h;
    }
}

__global__ void delta_kernel(const float* __restrict__ boxreg, const float* __restrict__ refine,
                             float* __restrict__ out)
{
    const int idx = blockIdx.x * blockDim.x + threadIdx.x;
    if (idx >= 2 * 36 * HW) return;
    const int p = idx % HW, ch = (idx / HW) % 36, b = idx / (36 * HW), c = ch & 3;
    const float o1 = boxreg[((size_t)b * 36 + ch) * HW + p];
    const float o2 = refine[((size_t)b * 36 + ch) * HW + p];
    float v;
    if (c < 2) v = o1 + expf(boxreg[((size_t)b * 36 + ch + 2) * HW + p]) * o2;
    else       v = o1 + o2;
    out[idx] = v;
}

#define W_CLS   0
#define W_REG   1024
#define W_PRED  2048
#define W_DCLS  2176
#define W_DREG  2432
#define W_LOGIT 2688
#define W_REFIN 3456

#define NT_CONV 88

extern "C" void kernel_launch(void* const* d_in, const int* in_sizes, int n_in,
                              void* d_out, int out_size)
{
    const float* x        = (const float*)d_in[0];
    const float* cls_w    = (const float*)d_in[1];
    const float* cls_b    = (const float*)d_in[2];
    const float* reg_w    = (const float*)d_in[3];
    const float* reg_b    = (const float*)d_in[4];
    const float* pred_w   = (const float*)d_in[5];
    const float* pred_b   = (const float*)d_in[6];
    const float* dcls_w   = (const float*)d_in[7];
    const float* dreg_w   = (const float*)d_in[8];
    const float* logit_w  = (const float*)d_in[9];
    const float* logit_b  = (const float*)d_in[10];
    const float* refine_w = (const float*)d_in[11];
    const float* refine_b = (const float*)d_in[12];

    __half *wfh, *wfl, *catc, *catr, *fA, *fB;
    float *f32, *boxreg, *refine;
    cudaGetSymbolAddress((void**)&wfh, g_wfh);
    cudaGetSymbolAddress((void**)&wfl, g_wfl);
    cudaGetSymbolAddress((void**)&catc, g_catc);
    cudaGetSymbolAddress((void**)&catr, g_catr);
    cudaGetSymbolAddress((void**)&fA, g_fA);
    cudaGetSymbolAddress((void**)&fB, g_fB);
    cudaGetSymbolAddress((void**)&f32, g_f32);
    cudaGetSymbolAddress((void**)&boxreg, g_boxreg);
    cudaGetSymbolAddress((void**)&refine, g_refine);
    fA += FGUARD; fB += FGUARD;

    cudaFuncSetAttribute(gemm_f16, cudaFuncAttributeMaxDynamicSharedMemorySize, SMEM_F);
    cudaFuncSetAttribute(conv_f16, cudaFuncAttributeMaxDynamicSharedMemorySize, SMEM_F);
    cudaFuncSetAttribute(deform_conv_f16, cudaFuncAttributeMaxDynamicSharedMemorySize, SMEM_D);

    auto wsp = [&](const float* src, int rowoff, int M, int Mp, int tap) {
        wsplit_f16<<<(Mp * KTOT + 255) / 256, 256>>>(
            src, wfh + (size_t)rowoff * KTOT, wfl + (size_t)rowoff * KTOT, M, Mp, tap);
    };
    wsp(cls_w, W_CLS, 1024, 1024, 1);
    wsp(reg_w, W_REG, 1024, 1024, 1);
    xsplit3_f16<<<(2 * 256 * NPIX + 255) / 256, 256>>>(x, fB);

    // ---- towers ----
    struct { const __half* in; int cshift; __half* out; int xf; } L[4] = {
        {fB, 1, fA, 0}, {fA, 0, fB, 0}, {fB, 0, fA, 0}, {fA, 0, fB, 64}};
    for (int layer = 0; layer < 4; layer++) {
        dim3 grid(NT_CONV, 2, 4);
        conv_f16<<<grid, 256, SMEM_F>>>(
            wfh, wfl, W_CLS + layer * 256, W_REG + layer * 256,
            L[layer].in, 1, 0, L[layer].cshift,
            cls_b + layer * 256, reg_b + layer * 256,
            nullptr, 0, L[layer].out, f32,
            256, 1 | 2 | 8 | 16 | L[layer].xf);
    }

    wsp(pred_w, W_PRED, 36, 128, 1);
    wsp(dcls_w, W_DCLS, 256, 256, 1);   // tap-major for fused deform
    wsp(dreg_w, W_DREG, 256, 256, 1);
    wsp(logit_w, W_LOGIT, 720, 768, 0);
    wsp(refine_w, W_REFIN, 36, 128, 0);

    // ---- pred conv ----
    {
        dim3 grid(NT_CONV, 1, 2);
        conv_f16<<<grid, 256, SMEM_F>>>(
            wfh, wfl, W_PRED, W_PRED,
            fB, 2, 1, 0,
            pred_b, pred_b,
            boxreg, (size_t)36 * HW, nullptr, nullptr, 36, 1 | 32);
    }

    // ---- fused deform: ONE launch, no col tensor, no side stream ----
    {
        dim3 grid(NPAD / 128, 2, 36);
        deform_conv_f16<<<grid, 256, SMEM_D>>>(
            wfh, wfl, W_DCLS, W_DREG, f32, boxreg, catc, catr);
    }

    // ---- 1x1 heads ----
    float* logits_out = (float*)d_out;
    float* delta_out = logits_out + (size_t)2 * 720 * HW;
    {
        dim3 gl(NPAD / 128, 6, 2);
        gemm_f16<<<gl, 256, SMEM_F>>>(
            wfh, wfl, W_LOGIT, catc, logit_b, logits_out, (size_t)720 * HW, 720);
        dim3 gr(NPAD / 128, 1, 2);
        gemm_f16<<<gr, 256, SMEM_F>>>(
            wfh, wfl, W_REFIN, catr, refine_b, refine, (size_t)36 * HW, 36);
    }

    delta_kernel<<<(2 * 36 * HW + 255) / 256, 256>>>(boxreg, refine, delta_out);
}

// round 17
// speedup vs baseline: 1.0824x; 1.0824x over previous
#include <cuda_runtime.h>
#include <cuda_fp16.h>
#include <cstdint>
#include <cstddef>

#define HW    10000
#define WID   100
#define NPAD  10240
#define KTOT  2304
#define WROWS 3584
#define CSTR  ((size_t)NPAD * KTOT)
#define CH112 11312
#define NPIX  11200
#define FC4   ((size_t)4 * 256 * CH112)
#define FGUARD 128

__device__ __half g_wfh[WROWS * KTOT];
__device__ __half g_wfl[WROWS * KTOT];
__device__ __half g_colf[12 * CSTR];
__device__ __half g_catc[2 * CSTR];
__device__ __half g_catr[2 * CSTR];
__device__ __half g_fA[FGUARD + 3 * FC4 + 256];
__device__ __half g_fB[FGUARD + 3 * FC4 + 256];
__device__ float g_f32[(size_t)4 * 256 * CH112];
__device__ int2   g_toff[(size_t)18 * 9 * HW];   // bilinear offsets (o00, packed dx|dy)
__device__ float4 g_twt[(size_t)18 * 9 * HW];    // bilinear weights
__device__ float g_boxreg[2 * 36 * HW];
__device__ float g_refine[2 * 36 * HW];

__constant__ float c_AW[9] = {
    2.8284271247461903f, 2.0f, 1.4142135623730951f,
    3.5635948725613580f, 2.5198420997897464f, 1.7817974362806790f,
    4.4898481932374910f, 3.1748021039363988f, 2.2449240966187455f};
__constant__ float c_AH[9] = {
    1.4142135623730951f, 2.0f, 2.8284271247461903f,
    1.7817974362806790f, 2.5198420997897464f, 3.5635948725613580f,
    2.2449240966187455f, 3.1748021039363988f, 4.4898481932374910f};
__constant__ int c_dy9[9]   = {-1,-1,-1, 0,0,0, 1,1,1};
__constant__ int c_dxsel[9] = { 0, 1, 2, 0,1,2, 0,1,2};

__device__ __forceinline__ uint32_t smem_u32(const void* p) {
    uint32_t a;
    asm("{ .reg .u64 t; cvta.to.shared.u64 t, %1; cvt.u32.u64 %0, t; }" : "=r"(a) : "l"(p));
    return a;
}
__device__ __forceinline__ void cp16(uint32_t dst, const void* src) {
    asm volatile("cp.async.cg.shared.global [%0], [%1], 16;" :: "r"(dst), "l"(src));
}
__device__ __forceinline__ void ldmx4(uint32_t* r, uint32_t addr) {
    asm volatile("ldmatrix.sync.aligned.m8n8.x4.shared.b16 {%0,%1,%2,%3}, [%4];"
                 : "=r"(r[0]), "=r"(r[1]), "=r"(r[2]), "=r"(r[3]) : "r"(addr));
}
__device__ __forceinline__ void ldmx4t(uint32_t* r, uint32_t addr) {
    asm volatile("ldmatrix.sync.aligned.m8n8.x4.trans.shared.b16 {%0,%1,%2,%3}, [%4];"
                 : "=r"(r[0]), "=r"(r[1]), "=r"(r[2]), "=r"(r[3]) : "r"(addr));
}
__device__ __forceinline__ void mma_hf(float* c, const uint32_t* a, uint32_t b0, uint32_t b1) {
    asm volatile("mma.sync.aligned.m16n8k16.row.col.f32.f16.f16.f32 "
                 "{%0,%1,%2,%3}, {%4,%5,%6,%7}, {%8,%9}, {%0,%1,%2,%3};"
                 : "+f"(c[0]), "+f"(c[1]), "+f"(c[2]), "+f"(c[3])
                 : "r"(a[0]), "r"(a[1]), "r"(a[2]), "r"(a[3]), "r"(b0), "r"(b1));
}
__device__ __forceinline__ uint32_t hpack(__half a, __half b) {
    return (uint32_t)__half_as_ushort(a) | ((uint32_t)__half_as_ushort(b) << 16);
}
__device__ __forceinline__ uint32_t sw_off(int r, int c) {
    return (uint32_t)((r * 4 + (c ^ (r & 3))) << 4);
}
__device__ __forceinline__ uint32_t swb_off(int r, int c) {
    return (uint32_t)((r * 16 + (c ^ (r & 7))) << 4);
}

#define TILE_B 8192
#define NSTG 3
#define NK   72
#define STAGE_F (3 * TILE_B)
#define SMEM_F (NSTG * STAGE_F)   // 72 KB -> 2 CTAs/SM

// ============ fp16 2-term GEMM, explicit B [rows,K] (deform + heads) ============
// flags: 1=bias(fp32 out)  4=cat-out  8=z-parity (deform: t=z&1 picks weights/cat)
__global__ __launch_bounds__(256, 2) void gemm_f16(
    const __half* __restrict__ Wh, const __half* __restrict__ Wl, int arowE, int arowO,
    const __half* __restrict__ Bbase,
    const float* __restrict__ bias,
    float* __restrict__ outF, size_t outStride,
    __half* __restrict__ catc, __half* __restrict__ catr,
    int M, int flags, int zoff)
{
    extern __shared__ char smem[];
    const uint32_t sb = smem_u32(smem);
    const int tid = threadIdx.x, lane = tid & 31, w = tid >> 5;
    const int wm = w >> 2, wn = w & 3;
    const int m0 = blockIdx.y * 128, n0 = blockIdx.x * 128;
    const int z = blockIdx.z;
    const int t = (flags & 8) ? (z & 1) : 0;
    const int arow = t ? arowO : arowE;

    const __half* srcA[2] = {Wh + ((size_t)arow + m0) * KTOT, Wl + ((size_t)arow + m0) * KTOT};
    const __half* srcB = Bbase + (size_t)z * CSTR + (size_t)n0 * KTOT;

    float acc[4][4][4];
#pragma unroll
    for (int i = 0; i < 4; i++)
#pragma unroll
        for (int j = 0; j < 4; j++)
#pragma unroll
            for (int q = 0; q < 4; q++) acc[i][j][q] = 0.f;

    const int ra = (lane & 15), ca = lane >> 4;
    const int rb = (lane & 7) + ((lane >> 4) << 3), cb = (lane >> 3) & 1;

#define LOAD_STAGE(s, k0) do { \
    _Pragma("unroll") \
    for (int tt = 0; tt < 2; tt++) { \
        const uint32_t base = sb + (uint32_t)((s) * STAGE_F + tt * TILE_B); \
        _Pragma("unroll") \
        for (int h = 0; h < 2; h++) { \
            const int q = tid + h * 256; \
            const int r = q >> 2, c = q & 3; \
            cp16(base + sw_off(r, c), srcA[tt] + (size_t)r * KTOT + (k0) + c * 8); \
        } \
    } \
    { \
        const uint32_t base = sb + (uint32_t)((s) * STAGE_F + 2 * TILE_B); \
        _Pragma("unroll") \
        for (int h = 0; h < 2; h++) { \
            const int q = tid + h * 256; \
            const int r = q >> 2, c = q & 3; \
            cp16(base + sw_off(r, c), srcB + (size_t)r * KTOT + (k0) + c * 8); \
        } \
    } \
} while (0)

    LOAD_STAGE(0, 0);
    asm volatile("cp.async.commit_group;" ::: "memory");
    LOAD_STAGE(1, 32);
    asm volatile("cp.async.commit_group;" ::: "memory");

    for (int kc = 0; kc < NK; kc++) {
        asm volatile("cp.async.wait_group 1;" ::: "memory");
        __syncthreads();
        const uint32_t bA  = sb + (uint32_t)((kc % NSTG) * STAGE_F);
        const uint32_t bAl = bA + TILE_B;
        const uint32_t bB  = bA + 2 * TILE_B;
#pragma unroll
        for (int kh = 0; kh < 2; kh++) {
            uint32_t fb[2][4];
#pragma unroll
            for (int nt2 = 0; nt2 < 2; nt2++) {
                const int rr = wn * 32 + nt2 * 16 + rb;
                ldmx4(fb[nt2], bB + sw_off(rr, kh * 2 + cb));
            }
#pragma unroll
            for (int mt = 0; mt < 4; mt++) {
                uint32_t fah[4], fal[4];
                const int rr = wm * 64 + mt * 16 + ra;
                ldmx4(fah, bA  + sw_off(rr, kh * 2 + ca));
                ldmx4(fal, bAl + sw_off(rr, kh * 2 + ca));
#pragma unroll
                for (int nt = 0; nt < 4; nt++) {
                    const uint32_t b0 = fb[nt >> 1][(nt & 1) * 2];
                    const uint32_t b1 = fb[nt >> 1][(nt & 1) * 2 + 1];
                    mma_hf(acc[mt][nt], fah, b0, b1);
                    mma_hf(acc[mt][nt], fal, b0, b1);
                }
            }
        }
        if (kc + 2 < NK) LOAD_STAGE((kc + 2) % NSTG, (kc + 2) * 32);
        asm volatile("cp.async.commit_group;" ::: "memory");
    }
    __syncthreads();
#undef LOAD_STAGE

    const int group = lane >> 2, tid4 = lane & 3;
    if (flags & 4) {
        const int dIdx = zoff + (z >> 1);
        const int bpp = dIdx / 9, ap = dIdx % 9;
        __half* outT = t ? catr : catc;
        float* smf = (float*)smem;
#pragma unroll
        for (int mt = 0; mt < 4; mt++)
#pragma unroll
            for (int nt = 0; nt < 4; nt++) {
                const int ml = wm * 64 + mt * 16 + group;
                const int nl = wn * 32 + nt * 8 + tid4 * 2;
                smf[nl * 128 + ml]           = acc[mt][nt][0];
                smf[(nl + 1) * 128 + ml]     = acc[mt][nt][1];
                smf[nl * 128 + ml + 8]       = acc[mt][nt][2];
                smf[(nl + 1) * 128 + ml + 8] = acc[mt][nt][3];
            }
        __syncthreads();
        const int nl = tid >> 1, half = tid & 1;
        const float* row = smf + nl * 128 + half * 64;
        __half* oh = outT + (size_t)(bpp * NPAD + n0 + nl) * KTOT + ap * 256 + m0 + half * 64;
#pragma unroll
        for (int g = 0; g < 8; g++) {
            __half hs[8];
#pragma unroll
            for (int j = 0; j < 8; j++)
                hs[j] = __float2half_rn(fmaxf(row[g * 8 + j], 0.f));
            *(uint4*)(oh + g * 8) = make_uint4(hpack(hs[0],hs[1]), hpack(hs[2],hs[3]),
                                               hpack(hs[4],hs[5]), hpack(hs[6],hs[7]));
        }
    } else {
        float* oF = outF + (size_t)z * outStride;
#pragma unroll
        for (int mt = 0; mt < 4; mt++) {
            const int mA = m0 + wm * 64 + mt * 16 + group;
            const int mB = mA + 8;
            const float bvA = ((flags & 1) && mA < M) ? bias[mA] : 0.f;
            const float bvB = ((flags & 1) && mB < M) ? bias[mB] : 0.f;
#pragma unroll
            for (int nt = 0; nt < 4; nt++) {
                const int n = n0 + wn * 32 + nt * 8 + tid4 * 2;
#pragma unroll
                for (int e = 0; e < 2; e++) {
                    if (n + e < HW) {
                        if (mA < M) oF[(size_t)mA * HW + n + e] = acc[mt][nt][e] + bvA;
                        if (mB < M) oF[(size_t)mB * HW + n + e] = acc[mt][nt][2 + e] + bvB;
                    }
                }
            }
        }
    }
}

// ============ fp16 2-term implicit conv GEMM (towers + pred) ============
// flags: 1=bias 2=relu 8=z-parity 16=feat-out 32=fp32-p-out 64=also f32 copy
__global__ __launch_bounds__(256, 2) void conv_f16(
    const __half* __restrict__ Wh, const __half* __restrict__ Wl, int arowE, int arowO,
    const __half* __restrict__ fIn, int cmul, int cadd, int cshift,
    const float* __restrict__ biasE, const float* __restrict__ biasO,
    float* __restrict__ outF, size_t outStride,
    __half* __restrict__ oFeat, float* __restrict__ oF32,
    int M, int flags)
{
    extern __shared__ char smem[];
    const uint32_t sb = smem_u32(smem);
    const int tid = threadIdx.x, lane = tid & 31, w = tid >> 5;
    const int wm = w >> 2, wn = w & 3;
    const int m0 = blockIdx.y * 128, n0 = blockIdx.x * 128;
    const int z = blockIdx.z;
    const int inChain = ((z * cmul) + cadd) >> cshift;

    const bool odd = (flags & 8) && (z & 1);
    const int arow = odd ? arowO : arowE;
    const float* bias = odd ? biasO : biasE;

    const __half* srcA[2] = {Wh + ((size_t)arow + m0) * KTOT, Wl + ((size_t)arow + m0) * KTOT};
    const __half* fbase = fIn + (size_t)inChain * 256 * CH112 + n0;

    float acc[4][4][4];
#pragma unroll
    for (int i = 0; i < 4; i++)
#pragma unroll
        for (int j = 0; j < 4; j++)
#pragma unroll
            for (int q = 0; q < 4; q++) acc[i][j][q] = 0.f;

    const int ra = (lane & 15), ca = lane >> 4;

#define LOAD_CSTAGE(s, kc) do { \
    const int _t = (kc) >> 3, _c0 = ((kc) & 7) << 5; \
    const long _toff = (long)c_dxsel[_t] * (long)FC4 + (long)c_dy9[_t] * 112; \
    _Pragma("unroll") \
    for (int t2 = 0; t2 < 2; t2++) { \
        const uint32_t baseA = sb + (uint32_t)((s) * STAGE_F + t2 * TILE_B); \
        _Pragma("unroll") \
        for (int h = 0; h < 2; h++) { \
            const int q = tid + h * 256; \
            const int r = q >> 2, c = q & 3; \
            cp16(baseA + sw_off(r, c), srcA[t2] + (size_t)r * KTOT + (kc) * 32 + c * 8); \
        } \
    } \
    { \
        const uint32_t baseB = sb + (uint32_t)((s) * STAGE_F + 2 * TILE_B); \
        _Pragma("unroll") \
        for (int h = 0; h < 2; h++) { \
            const int q = tid + h * 256; \
            const int r = q >> 4, c = q & 15; \
            cp16(baseB + swb_off(r, c), fbase + _toff + (size_t)(_c0 + r) * CH112 + c * 8); \
        } \
    } \
} while (0)

    LOAD_CSTAGE(0, 0);
    asm volatile("cp.async.commit_group;" ::: "memory");
    LOAD_CSTAGE(1, 1);
    asm volatile("cp.async.commit_group;" ::: "memory");

    for (int kc = 0; kc < NK; kc++) {
        asm volatile("cp.async.wait_group 1;" ::: "memory");
        __syncthreads();
        const uint32_t bA  = sb + (uint32_t)((kc % NSTG) * STAGE_F);
        const uint32_t bAl = bA + TILE_B;
        const uint32_t bB  = bA + 2 * TILE_B;
#pragma unroll
        for (int kh = 0; kh < 2; kh++) {
            const int rowl = kh * 16 + (lane & 15);
            uint32_t fb[2][4];
#pragma unroll
            for (int nt2 = 0; nt2 < 2; nt2++) {
                const int chunk = wn * 4 + nt2 * 2 + (lane >> 4);
                ldmx4t(fb[nt2], bB + swb_off(rowl, chunk));
            }
#pragma unroll
            for (int mt = 0; mt < 4; mt++) {
                uint32_t fah[4], fal[4];
                const int rr = wm * 64 + mt * 16 + ra;
                ldmx4(fah, bA  + sw_off(rr, kh * 2 + ca));
                ldmx4(fal, bAl + sw_off(rr, kh * 2 + ca));
#pragma unroll
                for (int nt = 0; nt < 4; nt++) {
                    const uint32_t b0 = fb[nt >> 1][(nt & 1) * 2];
                    const uint32_t b1 = fb[nt >> 1][(nt & 1) * 2 + 1];
                    mma_hf(acc[mt][nt], fah, b0, b1);
                    mma_hf(acc[mt][nt], fal, b0, b1);
                }
            }
        }
        if (kc + 2 < NK) LOAD_CSTAGE((kc + 2) % NSTG, kc + 2);
        asm volatile("cp.async.commit_group;" ::: "memory");
    }
    __syncthreads();
#undef LOAD_CSTAGE

    const int group = lane >> 2, tid4 = lane & 3;
#pragma unroll
    for (int mt = 0; mt < 4; mt++) {
        const int mA = m0 + wm * 64 + mt * 16 + group;
        const int mB = mA + 8;
        const float bvA = ((flags & 1) && mA < M) ? bias[mA] : 0.f;
        const float bvB = ((flags & 1) && mB < M) ? bias[mB] : 0.f;
#pragma unroll
        for (int nt = 0; nt < 4; nt++) {
            const int n = n0 + wn * 32 + nt * 8 + tid4 * 2;
#pragma unroll
            for (int e = 0; e < 2; e++) {
                const int p2 = n + e;
                if (p2 >= NPIX) continue;
                const int xq = p2 % 112;
                if (xq >= 100) continue;
                if (flags & 16) {
#pragma unroll
                    for (int half = 0; half < 2; half++) {
                        const int m = half ? mB : mA;
                        float v = (half ? acc[mt][nt][2 + e] : acc[mt][nt][e]) + (half ? bvB : bvA);
                        v = fmaxf(v, 0.f);
                        const __half h = __float2half_rn(v);
                        const size_t cb = (size_t)(z * 256 + m) * CH112;
                        if (flags & 64) oF32[cb + p2] = v;
#pragma unroll
                        for (int j = 0; j < 3; j++) {
                            const int q = p2 - (j - 1);
                            if (q >= 0) oFeat[(size_t)j * FC4 + cb + q] = h;
                        }
                    }
                } else {
                    const int p = (p2 / 112) * 100 + xq;
                    float* oF = outF + (size_t)z * outStride;
                    if (mA < M) oF[(size_t)mA * HW + p] = acc[mt][nt][e] + bvA;
                    if (mB < M) oF[(size_t)mB * HW + p] = acc[mt][nt][2 + e] + bvB;
                }
            }
        }
    }
}

// ============ small kernels ============
__global__ void wsplit_f16(const float* __restrict__ src, __half* __restrict__ h,
                           __half* __restrict__ l, int M, int Mp, int tap)
{
    const int idx = blockIdx.x * blockDim.x + threadIdx.x;
    if (idx >= Mp * KTOT) return;
    const int m = idx / KTOT, kk = idx % KTOT;
    float v = 0.f;
    if (m < M) {
        const int ks = tap ? ((kk & 255) * 9 + (kk >> 8)) : kk;
        v = src[(size_t)m * KTOT + ks];
    }
    const __half hh = __float2half_rn(v);
    h[idx] = hh;
    l[idx] = __float2half_rn(v - __half2float(hh));
}

__global__ void xsplit3_f16(const float* __restrict__ x, __half* __restrict__ o)
{
    const int idx = blockIdx.x * blockDim.x + threadIdx.x;
    if (idx >= 2 * 256 * NPIX) return;
    const int p2 = idx % NPIX;
    const int ch = idx / NPIX;
    const int xq = p2 % 112;
    if (xq >= 100) return;
    const float v = x[(size_t)ch * HW + (p2 / 112) * 100 + xq];
    const __half h = __float2half_rn(v);
    const size_t cb = (size_t)ch * CH112;
#pragma unroll
    for (int j = 0; j < 3; j++) {
        const int q = p2 - (j - 1);
        if (q >= 0) o[(size_t)j * FC4 + cb + q] = h;
    }
}

// precompute bilinear tables for all 18 deform indices (identical fp32 math to R15)
__global__ void mk_table(const float* __restrict__ boxreg,
                         int2* __restrict__ toff, float4* __restrict__ twt)
{
    const int idx = blockIdx.x * blockDim.x + threadIdx.x;
    if (idx >= 18 * HW) return;
    const int dIdx = idx / HW, p = idx % HW;
    const int bpp = dIdx / 9, ap = dIdx % 9;
    const int nn = ap * 2 + bpp, bb = nn / 9, aa = nn % 9;
    const float aw = c_AW[aa], ah_ = c_AH[aa];
    const float* br = boxreg + (size_t)bb * 36 * HW + (size_t)aa * 4 * HW + p;
    const int y = p / WID, x = p % WID;
    const float r0 = br[0], r1 = br[HW], r2 = br[2 * HW], r3 = br[3 * HW];
    const float whx = aw * expf(r2), why = ah_ * expf(r3);
    const float tlx = aw * r0 - 0.5f * whx, tly = ah_ * r1 - 0.5f * why;
    const float gxv[3] = {tlx, tlx + 0.5f * whx, tlx + whx};
    const float gyv[3] = {tly, tly + 0.5f * why, tly + why};
    const size_t tb = (size_t)dIdx * 9 * HW;
#pragma unroll
    for (int i = 0; i < 3; i++) {
        const float pxf = (float)x + gyv[i];
        const float x0f = floorf(pxf);
        const float lx = pxf - x0f;
        const int ix0 = (int)x0f;
        const bool vx0 = (ix0 >= 0) && (ix0 < WID), vx1 = (ix0 + 1 >= 0) && (ix0 + 1 < WID);
        const int xc0 = min(max(ix0, 0), WID - 1), xc1 = min(max(ix0 + 1, 0), WID - 1);
#pragma unroll
        for (int j = 0; j < 3; j++) {
            const int k = i * 3 + j;
            const float pyf = (float)y + gxv[j];
            const float y0f = floorf(pyf);
            const float ly = pyf - y0f;
            const int iy0 = (int)y0f;
            const bool vy0 = (iy0 >= 0) && (iy0 < WID), vy1 = (iy0 + 1 >= 0) && (iy0 + 1 < WID);
            const int yc0 = min(max(iy0, 0), WID - 1), yc1 = min(max(iy0 + 1, 0), WID - 1);
            float4 wv;
            wv.x = (vy0 && vx0) ? (1.f - ly) * (1.f - lx) : 0.f;
            wv.y = (vy0 && vx1) ? (1.f - ly) * lx : 0.f;
            wv.z = (vy1 && vx0) ? ly * (1.f - lx) : 0.f;
            wv.w = (vy1 && vx1) ? ly * lx : 0.f;
            int2 ov;
            ov.x = yc0 * 112 + xc0;
            ov.y = (xc1 - xc0) | (((yc1 - yc0) * 112) << 16);
            toff[tb + (size_t)k * HW + p] = ov;
            twt[tb + (size_t)k * HW + p] = wv;
        }
    }
}

// fused deform gather (cls + reg) reading precomputed tables
__global__ __launch_bounds__(256) void im2col_def_f16(
    const float* __restrict__ f32,
    const int2* __restrict__ toff, const float4* __restrict__ twt,
    __half* __restrict__ colBase, int base3)
{
    const int zl = blockIdx.y;
    const int dIdx = base3 + zl;
    const int bpp = dIdx / 9;
    const int idx = blockIdx.x * 256 + threadIdx.x;
    if (idx >= NPAD * 32) return;
    const int p = idx % NPAD, cblk = idx / NPAD;
    __half* o0 = colBase + (size_t)(zl * 2)     * CSTR + (size_t)p * KTOT + cblk * 72;
    __half* o1 = colBase + (size_t)(zl * 2 + 1) * CSTR + (size_t)p * KTOT + cblk * 72;
    if (p >= HW) {
        const uint4 zz = make_uint4(0, 0, 0, 0);
#pragma unroll
        for (int g = 0; g < 9; g++) { *(uint4*)(o0 + g * 8) = zz; *(uint4*)(o1 + g * 8) = zz; }
        return;
    }
    // load 9-tap table (coalesced over p, L2-resident)
    const size_t tb = (size_t)dIdx * 9 * HW + p;
    int O00[9], DX[9], DY[9];
    float W00[9], W01[9], W10[9], W11[9];
#pragma unroll
    for (int k = 0; k < 9; k++) {
        const int2 ov = toff[tb + (size_t)k * HW];
        const float4 wv = twt[tb + (size_t)k * HW];
        O00[k] = ov.x;
        DX[k] = (short)(ov.y & 0xffff);
        DY[k] = ov.y >> 16;
        W00[k] = wv.x; W01[k] = wv.y; W10[k] = wv.z; W11[k] = wv.w;
    }
#pragma unroll
    for (int t = 0; t < 2; t++) {
        const float* f0 = f32 + (size_t)((bpp * 2 + t) * 256) * CH112;
        __half* out = t ? o1 : o0;
#pragma unroll 1
        for (int g = 0; g < 9; g++) {
            __half hs[8];
#pragma unroll
            for (int j = 0; j < 8; j++) {
                const int e = g * 8 + j, cc = e / 9, k = e - cc * 9;
                const float* f = f0 + (size_t)(cblk * 8 + cc) * CH112 + O00[k];
                hs[j] = __float2half_rn(W00[k] * f[0] + W01[k] * f[DX[k]]
                                      + W10[k] * f[DY[k]] + W11[k] * f[DX[k] + DY[k]]);
            }
            *(uint4*)(out + g * 8) = make_uint4(hpack(hs[0],hs[1]), hpack(hs[2],hs[3]),
                                                hpack(hs[4],hs[5]), hpack(hs[6],hs[7]));
        }
    }
}

__global__ void delta_kernel(const float* __restrict__ boxreg, const float* __restrict__ refine,
                             float* __restrict__ out)
{
    const int idx = blockIdx.x * blockDim.x + threadIdx.x;
    if (idx >= 2 * 36 * HW) return;
    const int p = idx % HW, ch = (idx / HW) % 36, b = idx / (36 * HW), c = ch & 3;
    const float o1 = boxreg[((size_t)b * 36 + ch) * HW + p];
    const float o2 = refine[((size_t)b * 36 + ch) * HW + p];
    float v;
    if (c < 2) v = o1 + expf(boxreg[((size_t)b * 36 + ch + 2) * HW + p]) * o2;
    else       v = o1 + o2;
    out[idx] = v;
}

#define W_CLS   0
#define W_REG   1024
#define W_PRED  2048
#define W_DCLS  2176
#define W_DREG  2432
#define W_LOGIT 2688
#define W_REFIN 3456

static cudaStream_t s_gather = nullptr;
static cudaEvent_t s_evG[6], s_evM[6], s_evFork, s_evJoin;
static void ensure_streams() {
    if (!s_gather) {
        cudaStreamCreateWithFlags(&s_gather, cudaStreamNonBlocking);
        for (int i = 0; i < 6; i++) {
            cudaEventCreateWithFlags(&s_evG[i], cudaEventDisableTiming);
            cudaEventCreateWithFlags(&s_evM[i], cudaEventDisableTiming);
        }
        cudaEventCreateWithFlags(&s_evFork, cudaEventDisableTiming);
        cudaEventCreateWithFlags(&s_evJoin, cudaEventDisableTiming);
    }
}

#define NT_CONV 88

extern "C" void kernel_launch(void* const* d_in, const int* in_sizes, int n_in,
                              void* d_out, int out_size)
{
    const float* x        = (const float*)d_in[0];
    const float* cls_w    = (const float*)d_in[1];
    const float* cls_b    = (const float*)d_in[2];
    const float* reg_w    = (const float*)d_in[3];
    const float* reg_b    = (const float*)d_in[4];
    const float* pred_w   = (const float*)d_in[5];
    const float* pred_b   = (const float*)d_in[6];
    const float* dcls_w   = (const float*)d_in[7];
    const float* dreg_w   = (const float*)d_in[8];
    const float* logit_w  = (const float*)d_in[9];
    const float* logit_b  = (const float*)d_in[10];
    const float* refine_w = (const float*)d_in[11];
    const float* refine_b = (const float*)d_in[12];

    __half *wfh, *wfl, *colf, *catc, *catr, *fA, *fB;
    int2* toff;
    float4* twt;
    float *f32, *boxreg, *refine;
    cudaGetSymbolAddress((void**)&wfh, g_wfh);
    cudaGetSymbolAddress((void**)&wfl, g_wfl);
    cudaGetSymbolAddress((void**)&colf, g_colf);
    cudaGetSymbolAddress((void**)&catc, g_catc);
    cudaGetSymbolAddress((void**)&catr, g_catr);
    cudaGetSymbolAddress((void**)&fA, g_fA);
    cudaGetSymbolAddress((void**)&fB, g_fB);
    cudaGetSymbolAddress((void**)&f32, g_f32);
    cudaGetSymbolAddress((void**)&toff, g_toff);
    cudaGetSymbolAddress((void**)&twt, g_twt);
    cudaGetSymbolAddress((void**)&boxreg, g_boxreg);
    cudaGetSymbolAddress((void**)&refine, g_refine);
    fA += FGUARD; fB += FGUARD;

    cudaFuncSetAttribute(gemm_f16, cudaFuncAttributeMaxDynamicSharedMemorySize, SMEM_F);
    cudaFuncSetAttribute(conv_f16, cudaFuncAttributeMaxDynamicSharedMemorySize, SMEM_F);
    ensure_streams();

    auto wsp = [&](const float* src, int rowoff, int M, int Mp, int tap) {
        wsplit_f16<<<(Mp * KTOT + 255) / 256, 256>>>(
            src, wfh + (size_t)rowoff * KTOT, wfl + (size_t)rowoff * KTOT, M, Mp, tap);
    };
    wsp(cls_w, W_CLS, 1024, 1024, 1);
    wsp(reg_w, W_REG, 1024, 1024, 1);
    xsplit3_f16<<<(2 * 256 * NPIX + 255) / 256, 256>>>(x, fB);

    // ---- towers ----
    struct { const __half* in; int cshift; __half* out; int xf; } L[4] = {
        {fB, 1, fA, 0}, {fA, 0, fB, 0}, {fB, 0, fA, 0}, {fA, 0, fB, 64}};
    for (int layer = 0; layer < 4; layer++) {
        dim3 grid(NT_CONV, 2, 4);
        conv_f16<<<grid, 256, SMEM_F>>>(
            wfh, wfl, W_CLS + layer * 256, W_REG + layer * 256,
            L[layer].in, 1, 0, L[layer].cshift,
            cls_b + layer * 256, reg_b + layer * 256,
            nullptr, 0, L[layer].out, f32,
            256, 1 | 2 | 8 | 16 | L[layer].xf);
    }

    wsp(pred_w, W_PRED, 36, 128, 1);
    wsp(dcls_w, W_DCLS, 256, 256, 0);
    wsp(dreg_w, W_DREG, 256, 256, 0);
    wsp(logit_w, W_LOGIT, 720, 768, 0);
    wsp(refine_w, W_REFIN, 36, 128, 0);

    // ---- pred conv (rf chains = fB chains 1,3) ----
    {
        dim3 grid(NT_CONV, 1, 2);
        conv_f16<<<grid, 256, SMEM_F>>>(
            wfh, wfl, W_PRED, W_PRED,
            fB, 2, 1, 0,
            pred_b, pred_b,
            boxreg, (size_t)36 * HW, nullptr, nullptr, 36, 1 | 32);
    }

    // ---- bilinear tables (all 18 dIdx) ----
    mk_table<<<(18 * HW + 255) / 256, 256>>>(boxreg, toff, twt);

    // ---- deform: 6 fused phases (table-driven gathers on side stream) ----
    {
        cudaEventRecord(s_evFork, 0);
        cudaStreamWaitEvent(s_gather, s_evFork, 0);
        const dim3 icg3(NPAD * 32 / 256, 3);
        const dim3 grid(NPAD / 128, 2, 6);
        for (int ph = 0; ph < 6; ph++) {
            const int base3 = ph * 3;
            __half* cb = colf + (size_t)(ph & 1) * 6 * CSTR;
            if (ph >= 2) cudaStreamWaitEvent(s_gather, s_evM[ph - 2], 0);
            im2col_def_f16<<<icg3, 256, 0, s_gather>>>(f32, toff, twt, cb, base3);
            cudaEventRecord(s_evG[ph], s_gather);
            cudaStreamWaitEvent(0, s_evG[ph], 0);
            gemm_f16<<<grid, 256, SMEM_F>>>(
                wfh, wfl, W_DCLS, W_DREG, cb, nullptr, nullptr, 0,
                catc, catr, 256, 4 | 8, base3);
            cudaEventRecord(s_evM[ph], 0);
        }
        cudaEventRecord(s_evJoin, s_gather);
        cudaStreamWaitEvent(0, s_evJoin, 0);
    }

    // ---- 1x1 heads ----
    float* logits_out = (float*)d_out;
    float* delta_out = logits_out + (size_t)2 * 720 * HW;
    {
        dim3 gl(NPAD / 128, 6, 2);
        gemm_f16<<<gl, 256, SMEM_F>>>(
            wfh, wfl, W_LOGIT, W_LOGIT, catc, logit_b,
            logits_out, (size_t)720 * HW, nullptr, nullptr, 720, 1, 0);
        dim3 gr(NPAD / 128, 1, 2);
        gemm_f16<<<gr, 256, SMEM_F>>>(
            wfh, wfl, W_REFIN, W_REFIN, catr, refine_b,
            refine, (size_t)36 * HW, nullptr, nullptr, 36, 1, 0);
    }

    delta_kernel<<<(2 * 36 * HW + 255) / 256, 256>>>(boxreg, refine, delta_out);
}